// round 14
// baseline (speedup 1.0000x reference)
#include <cuda_runtime.h>
#include <cuda.h>
#include <cstdint>

typedef unsigned long long u64;
typedef unsigned int u32;

#define LSEQ    2048
#define DIM     32
#define CL      5             // consecutive rows per lane (5 coprime 8 -> conflict-free under SW128)
#define CHUNK   160           // CL * 32
#define SROWS   161           // CHUNK + 1 boundary row
#define ROWB    128           // bytes per row in smem (natural, TMA SW128)
#define TXB     (SROWS * ROWB)   // 20608 bytes per TMA box
#define BUFB    21504         // buffer padded to 1024B multiple
#define NTILES  10
#define NWARPS  5
#define NTHREADS 160
#define HALFL   1024
#define NCHUNK  7
#define OUTD    528

__constant__ int c_i0[NTILES] = {0,0,0,0,8, 8,8,16,16,24};
__constant__ int c_j0[NTILES] = {0,8,16,24,8, 16,24,16,24,24};

__device__ __forceinline__ u64 pk2(float lo, float hi) {
    u64 r; asm("mov.b64 %0, {%1, %2};" : "=l"(r) : "f"(lo), "f"(hi)); return r;
}
__device__ __forceinline__ void upk2(u64 v, float& a, float& b) {
    asm("mov.b64 {%0, %1}, %2;" : "=f"(a), "=f"(b) : "l"(v));
}
__device__ __forceinline__ u64 fma2(u64 a, u64 b, u64 c) {
    u64 r; asm("fma.rn.f32x2 %0, %1, %2, %3;" : "=l"(r) : "l"(a), "l"(b), "l"(c)); return r;
}
__device__ __forceinline__ u64 add2(u64 a, u64 b) {
    u64 r; asm("add.rn.f32x2 %0, %1, %2;" : "=l"(r) : "l"(a), "l"(b)); return r;
}
__device__ __forceinline__ u64 swp(u64 v) {
    u32 a, b; asm("mov.b64 {%0, %1}, %2;" : "=r"(a), "=r"(b) : "l"(v));
    u64 r;    asm("mov.b64 %0, {%1, %2};" : "=l"(r) : "r"(b), "r"(a));
    return r;
}

__device__ __forceinline__ void mbar_init(u32 a, u32 cnt) {
    asm volatile("mbarrier.init.shared.b64 [%0], %1;" :: "r"(a), "r"(cnt) : "memory");
}
__device__ __forceinline__ void mbar_expect(u32 a, u32 tx) {
    asm volatile("mbarrier.arrive.expect_tx.shared.b64 _, [%0], %1;" :: "r"(a), "r"(tx) : "memory");
}
__device__ __forceinline__ void mbar_wait(u32 a, u32 parity) {
    asm volatile(
        "{\n\t.reg .pred P;\n\t"
        "WL_%=:\n\t"
        "mbarrier.try_wait.parity.acquire.cta.shared::cta.b64 P, [%0], %1, 0x989680;\n\t"
        "@P bra WD_%=;\n\t"
        "bra WL_%=;\n\t"
        "WD_%=:\n\t}"
        :: "r"(a), "r"(parity) : "memory");
}
__device__ __forceinline__ void tma3d(u32 dst, const CUtensorMap* m, int cx, int cy, int cz, u32 mbar) {
    asm volatile(
        "cp.async.bulk.tensor.3d.shared::cta.global.tile.mbarrier::complete_tx::bytes "
        "[%0], [%1, {%2, %3, %4}], [%5];"
        :: "r"(dst), "l"(m), "r"(cx), "r"(cy), "r"(cz), "r"(mbar) : "memory");
}

// load one 8-wide slice (32B) of row r as 4 packed pairs, SW128-aware (two 16B loads)
__device__ __forceinline__ void lds2(u64 (&v)[4], const char* buf, int r, int c0) {
    int sw = (r & 7) << 4;
    ulonglong2 a = *reinterpret_cast<const ulonglong2*>(buf + r * ROWB + (c0 ^ sw));
    ulonglong2 b = *reinterpret_cast<const ulonglong2*>(buf + r * ROWB + ((c0 + 16) ^ sw));
    v[0]=a.x; v[1]=a.y; v[2]=b.x; v[3]=b.y;
}

__global__ void zero_out_kernel(float* __restrict__ out, int n) {
    int i = blockIdx.x * blockDim.x + threadIdx.x;
    if (i < n) out[i] = 0.0f;
}

// Parity-pair accumulation (identical math to the passing R9 kernel).
template<bool DIAG, bool FULL>
__device__ __forceinline__ void chunk_compute(
    const char* __restrict__ buf, int r0, int l0l, int hi,
    int ci0, int cj0, u64 (&aee)[4][4], u64 (&aeo)[4][4], u64 m1)
{
    u64 ci2[4], cj2[4];
    lds2(ci2, buf, r0, ci0);
    if (!DIAG) lds2(cj2, buf, r0, cj0);

#pragma unroll
    for (int t = 0; t < CL; t++) {
        int rn = r0 + t + 1;
        u64 ni2[4], nj2[4];
        lds2(ni2, buf, rn, ci0);
        if (!DIAG) lds2(nj2, buf, rn, cj0);

        u64 d2[4];
#pragma unroll
        for (int q = 0; q < 4; q++)
            d2[q] = fma2(DIAG ? ci2[q] : cj2[q], m1, DIAG ? ni2[q] : nj2[q]);
        if (!FULL) {
            u64 m = (u64)0 - (u64)(l0l + t < hi);
#pragma unroll
            for (int q = 0; q < 4; q++) d2[q] &= m;
        }
        u64 s2[4], sw[4];
#pragma unroll
        for (int p = 0; p < 4; p++) { s2[p] = add2(ci2[p], ni2[p]); sw[p] = swp(s2[p]); }

#pragma unroll
        for (int p = 0; p < 4; p++)
#pragma unroll
            for (int q = 0; q < 4; q++) {
                if (!DIAG || q > p)  aee[p][q] = fma2(s2[p], d2[q], aee[p][q]);
                if (!DIAG || q >= p) aeo[p][q] = fma2(sw[p], d2[q], aeo[p][q]);
            }
#pragma unroll
        for (int k = 0; k < 4; k++) ci2[k] = ni2[k];
        if (!DIAG) {
#pragma unroll
            for (int k = 0; k < 4; k++) cj2[k] = nj2[k];
        }
    }
}

__global__ __launch_bounds__(NTHREADS, 3)
void logsig_main(const __grid_constant__ CUtensorMap tmap,
                 const float* __restrict__ x, float* __restrict__ out)
{
    __shared__ __align__(1024) char sbuf[2][BUFB];
    __shared__ u64 mb[2];
    __shared__ float sx0[DIM];
    __shared__ float sxL[DIM];

    const int b    = blockIdx.x >> 2;
    const int sub  = blockIdx.x & 3;        // {half, tileset}
    const int half = sub >> 1;
    const int ts   = sub & 1;
    const int tid  = threadIdx.x;
    const int wid  = tid >> 5;
    const int lane = tid & 31;

    const float* __restrict__ xb = x + (size_t)b * (LSEQ * DIM);

    if (tid < DIM)            sx0[tid]       = xb[tid];
    else if (tid < 2 * DIM)   sxL[tid - DIM] = xb[(size_t)(LSEQ - 1) * DIM + (tid - DIM)];

    const int lo = half * HALFL;
    const int hi = (half == 0) ? HALFL : (LSEQ - 1);

    const int tile = ts * NWARPS + wid;
    const int i0 = c_i0[tile];
    const int j0 = c_j0[tile];
    const int ci0 = i0 * 4, cj0 = j0 * 4;   // byte offsets within a row
    const bool diag = (i0 == j0);
    const u64 m1 = pk2(-1.0f, -1.0f);

    u32 mbar[2];
    mbar[0] = (u32)__cvta_generic_to_shared(&mb[0]);
    mbar[1] = (u32)__cvta_generic_to_shared(&mb[1]);
    u32 sdst[2];
    sdst[0] = (u32)__cvta_generic_to_shared(&sbuf[0][0]);
    sdst[1] = (u32)__cvta_generic_to_shared(&sbuf[1][0]);

    if (tid == 0) {
        mbar_init(mbar[0], 1);
        mbar_init(mbar[1], 1);
        asm volatile("fence.proxy.async.shared::cta;" ::: "memory");
    }
    __syncthreads();

    u64 aee[4][4], aeo[4][4];
#pragma unroll
    for (int p = 0; p < 4; p++)
#pragma unroll
        for (int q = 0; q < 4; q++) { aee[p][q] = 0ull; aeo[p][q] = 0ull; }

    // issue chunk 0
    if (tid == 0) {
        mbar_expect(mbar[0], TXB);
        tma3d(sdst[0], &tmap, 0, lo, b, mbar[0]);
    }

    for (int c = 0; c < NCHUNK; c++) {
        if (c + 1 < NCHUNK && tid == 0) {
            int bi = (c + 1) & 1;
            mbar_expect(mbar[bi], TXB);
            tma3d(sdst[bi], &tmap, 0, lo + (c + 1) * CHUNK, b, mbar[bi]);
        }

        mbar_wait(mbar[c & 1], (c >> 1) & 1);

        const char* buf = sbuf[c & 1];
        const int r0  = lane * CL;
        const int l0l = lo + c * CHUNK + lane * CL;

        if (c < NCHUNK - 1) {
            if (diag) chunk_compute<true , true >(buf, r0, l0l, hi, ci0, cj0, aee, aeo, m1);
            else      chunk_compute<false, true >(buf, r0, l0l, hi, ci0, cj0, aee, aeo, m1);
        } else {
            if (diag) chunk_compute<true , false>(buf, r0, l0l, hi, ci0, cj0, aee, aeo, m1);
            else      chunk_compute<false, false>(buf, r0, l0l, hi, ci0, cj0, aee, aeo, m1);
        }

        __syncthreads();   // all warps done reading buf before it is re-targeted
    }

    // warp-level butterfly reduction over the 32 l-slices
#pragma unroll
    for (int p = 0; p < 4; p++)
#pragma unroll
        for (int q = 0; q < 4; q++) {
            u64 v = aee[p][q];
#pragma unroll
            for (int off = 16; off > 0; off >>= 1)
                v = add2(v, __shfl_xor_sync(0xFFFFFFFFu, v, off));
            aee[p][q] = v;
            u64 w = aeo[p][q];
#pragma unroll
            for (int off = 16; off > 0; off >>= 1)
                w = add2(w, __shfl_xor_sync(0xFFFFFFFFu, w, off));
            aeo[p][q] = w;
        }

    float* outb = out + (size_t)b * OUTD;

    if (sub == 0 && wid == 0) outb[lane] = sxL[lane] - sx0[lane];

    // areas writeout: e = {bank, p, q, h}
#pragma unroll
    for (int e2 = 0; e2 < 2; e2++) {
        int e    = lane + 32 * e2;
        int bank = e >> 5;
        int p    = (e >> 3) & 3;
        int q    = (e >> 1) & 3;
        int h    = e & 1;
        int i, j;
        if (bank == 0) { i = i0 + 2 * p + h;       j = j0 + 2 * q + h; }
        else           { i = i0 + 2 * p + (1 - h); j = j0 + 2 * q + h; }
        if (j > i) {
            float v0, v1;
            upk2(bank == 0 ? aee[p][q] : aeo[p][q], v0, v1);
            float C   = h ? v1 : v0;
            float val = 0.5f * C;
            if (half == 0) {
                float x0i = sx0[i];
                float li  = sxL[i] - x0i;
                float lj  = sxL[j] - sx0[j];
                val -= x0i * lj + 0.5f * li * lj;
            }
            int idx = DIM + i * (2 * DIM - 1 - i) / 2 + (j - i - 1);
            atomicAdd(&outb[idx], val);
        }
    }
}

typedef CUresult (*EncodeTiledFn)(
    CUtensorMap*, CUtensorMapDataType, cuuint32_t, void*,
    const cuuint64_t*, const cuuint64_t*, const cuuint32_t*, const cuuint32_t*,
    CUtensorMapInterleave, CUtensorMapSwizzle, CUtensorMapL2promotion, CUtensorMapFloatOOBfill);

extern "C" void kernel_launch(void* const* d_in, const int* in_sizes, int n_in,
                              void* d_out, int out_size)
{
    const float* x = (const float*)d_in[0];
    float* out = (float*)d_out;
    const int B = in_sizes[0] / (LSEQ * DIM);

    // Build the TMA descriptor (pure host-CPU work; graph-capture safe)
    void* fp = nullptr;
    cudaDriverEntryPointQueryResult st;
    cudaGetDriverEntryPointByVersion("cuTensorMapEncodeTiled", &fp, 12000,
                                     cudaEnableDefault, &st);
    EncodeTiledFn enc = (EncodeTiledFn)fp;

    CUtensorMap tmap;
    cuuint64_t dims[3]    = {DIM, LSEQ, (cuuint64_t)B};
    cuuint64_t strides[2] = {DIM * 4ull, (cuuint64_t)LSEQ * DIM * 4ull};
    cuuint32_t box[3]     = {DIM, SROWS, 1};
    cuuint32_t es[3]      = {1, 1, 1};
    enc(&tmap, CU_TENSOR_MAP_DATA_TYPE_FLOAT32, 3, (void*)x,
        dims, strides, box, es,
        CU_TENSOR_MAP_INTERLEAVE_NONE, CU_TENSOR_MAP_SWIZZLE_128B,
        CU_TENSOR_MAP_L2_PROMOTION_L2_128B, CU_TENSOR_MAP_FLOAT_OOB_FILL_NONE);

    zero_out_kernel<<<(out_size + 255) / 256, 256>>>(out, out_size);
    logsig_main<<<4 * B, NTHREADS>>>(tmap, x, out);
}